// round 1
// baseline (speedup 1.0000x reference)
#include <cuda_runtime.h>

// ---------------------------------------------------------------------------
// HEAQNetwork: 4-qubit, 3-layer hardware-efficient ansatz, batch = 1M.
// One thread per batch element; 16 complex amplitudes live in registers.
// Qubit q maps to bit (3-q) of the amplitude index (reference uses axis q+1,
// qubit 0 = most significant).
// ---------------------------------------------------------------------------

#define NQ 4
#define NL 3
#define QBIT(q) (1 << (3 - (q)))

__device__ float g_cw[NL * NQ];
__device__ float g_sw[NL * NQ];

// Precompute cos/sin of half the (shared) RY weight angles.
__global__ void prep_weights_kernel(const float* __restrict__ w) {
    int i = threadIdx.x;
    if (i < NL * NQ) {
        float h = 0.5f * w[i];
        g_cw[i] = cosf(h);
        g_sw[i] = sinf(h);
    }
}

template <int Q>
__device__ __forceinline__ void apply_rx(float sr[16], float si[16], float c, float s) {
    const float ns = -s;
#pragma unroll
    for (int i = 0; i < 16; i++) {
        if (i & QBIT(Q)) continue;
        const int j = i | QBIT(Q);
        float a0r = sr[i], a0i = si[i], a1r = sr[j], a1i = si[j];
        sr[i] = fmaf(s,  a1i, c * a0r);
        si[i] = fmaf(ns, a1r, c * a0i);
        sr[j] = fmaf(s,  a0i, c * a1r);
        si[j] = fmaf(ns, a0r, c * a1i);
    }
}

template <int Q>
__device__ __forceinline__ void apply_ry(float sr[16], float si[16], float c, float s) {
    const float ns = -s;
#pragma unroll
    for (int i = 0; i < 16; i++) {
        if (i & QBIT(Q)) continue;
        const int j = i | QBIT(Q);
        float a0r = sr[i], a0i = si[i], a1r = sr[j], a1i = si[j];
        sr[i] = fmaf(ns, a1r, c * a0r);
        si[i] = fmaf(ns, a1i, c * a0i);
        sr[j] = fmaf(s,  a0r, c * a1r);
        si[j] = fmaf(s,  a0i, c * a1i);
    }
}

template <int C, int T>
__device__ __forceinline__ void apply_cnot(float sr[16], float si[16]) {
#pragma unroll
    for (int i = 0; i < 16; i++) {
        if (!(i & QBIT(C))) continue;   // control must be 1
        if (i & QBIT(T)) continue;      // visit each pair once (target=0 side)
        const int j = i | QBIT(T);
        float tr = sr[i]; sr[i] = sr[j]; sr[j] = tr;
        float ti = si[i]; si[i] = si[j]; si[j] = ti;
    }
}

__global__ void __launch_bounds__(256)
qsim_kernel(const float* __restrict__ x,
            const float* __restrict__ w_input,
            const float* __restrict__ w_output,
            float* __restrict__ out,
            int B) {
    int b = blockIdx.x * blockDim.x + threadIdx.x;
    if (b >= B) return;

    // ---- per-element RX angle trig: c = cos(atan(t)/2), s = sin(atan(t)/2)
    // via stable tan-half-angle: u = t / (1 + sqrt(1+t^2)); c = rsqrt(1+u^2); s = u*c
    const float4 xv = reinterpret_cast<const float4*>(x)[b];
    float t0 = xv.x * __ldg(&w_input[0]);
    float t1 = xv.y * __ldg(&w_input[1]);
    float t2 = xv.z * __ldg(&w_input[2]);
    float t3 = xv.w * __ldg(&w_input[3]);

    float ca[4], sa[4];
    {
        float tq[4] = {t0, t1, t2, t3};
#pragma unroll
        for (int q = 0; q < 4; q++) {
            float tt = tq[q];
            float u = tt / (1.0f + sqrtf(fmaf(tt, tt, 1.0f)));
            float r = rsqrtf(fmaf(u, u, 1.0f));
            ca[q] = r;
            sa[q] = u * r;
        }
    }

    // ---- Layer 0 shortcut: state after RX+RY layer on |0000> is a product state.
    // Per-qubit vector: v = RY(w) * RX(a)|0> = (cw*ca + i*sw*sa,  sw*ca - i*cw*sa)
    float vr[4][2], vi[4][2];
#pragma unroll
    for (int q = 0; q < 4; q++) {
        float cw = g_cw[q], sw = g_sw[q];
        vr[q][0] = cw * ca[q];
        vi[q][0] = sw * sa[q];
        vr[q][1] = sw * ca[q];
        vi[q][1] = -cw * sa[q];
    }

    // tensor product: qubits (0,1) -> h[4], qubits (2,3) -> l[4]
    float hr[4], hi[4], lr[4], li[4];
#pragma unroll
    for (int k = 0; k < 4; k++) {
        int b0 = k >> 1, b1 = k & 1;
        hr[k] = fmaf(vr[0][b0], vr[1][b1], -vi[0][b0] * vi[1][b1]);
        hi[k] = fmaf(vr[0][b0], vi[1][b1],  vi[0][b0] * vr[1][b1]);
        lr[k] = fmaf(vr[2][b0], vr[3][b1], -vi[2][b0] * vi[3][b1]);
        li[k] = fmaf(vr[2][b0], vi[3][b1],  vi[2][b0] * vr[3][b1]);
    }

    float sr[16], si[16];
#pragma unroll
    for (int i = 0; i < 16; i++) {
        int kh = i >> 2, kl = i & 3;
        sr[i] = fmaf(hr[kh], lr[kl], -hi[kh] * li[kl]);
        si[i] = fmaf(hr[kh], li[kl],  hi[kh] * lr[kl]);
    }

    // layer 0 CNOT chain
    apply_cnot<0, 1>(sr, si);
    apply_cnot<1, 2>(sr, si);
    apply_cnot<2, 3>(sr, si);

    // ---- Layers 1 and 2 (full gate application; RX trig reused across layers)
#pragma unroll
    for (int l = 1; l < NL; l++) {
        apply_rx<0>(sr, si, ca[0], sa[0]);
        apply_rx<1>(sr, si, ca[1], sa[1]);
        apply_rx<2>(sr, si, ca[2], sa[2]);
        apply_rx<3>(sr, si, ca[3], sa[3]);

        apply_ry<0>(sr, si, g_cw[l * 4 + 0], g_sw[l * 4 + 0]);
        apply_ry<1>(sr, si, g_cw[l * 4 + 1], g_sw[l * 4 + 1]);
        apply_ry<2>(sr, si, g_cw[l * 4 + 2], g_sw[l * 4 + 2]);
        apply_ry<3>(sr, si, g_cw[l * 4 + 3], g_sw[l * 4 + 3]);

        apply_cnot<0, 1>(sr, si);
        apply_cnot<1, 2>(sr, si);
        apply_cnot<2, 3>(sr, si);
    }

    // ---- probabilities and <Z0>, <Z1>
    float ez0 = 0.0f, ez1 = 0.0f;
#pragma unroll
    for (int i = 0; i < 16; i++) {
        float p = fmaf(sr[i], sr[i], si[i] * si[i]);
        ez0 += (i & 8) ? -p : p;   // qubit 0 = bit 3
        ez1 += (i & 4) ? -p : p;   // qubit 1 = bit 2
    }

    float wo0 = __ldg(&w_output[0]);
    float wo1 = __ldg(&w_output[1]);
    float2 o;
    o.x = (1.0f + ez0) * 0.5f * wo0;
    o.y = (1.0f + ez1) * 0.5f * wo1;
    reinterpret_cast<float2*>(out)[b] = o;
}

extern "C" void kernel_launch(void* const* d_in, const int* in_sizes, int n_in,
                              void* d_out, int out_size) {
    const float* x        = (const float*)d_in[0];  // (B, 4)
    const float* w_input  = (const float*)d_in[1];  // (4,)
    const float* weights  = (const float*)d_in[2];  // (3, 4)
    const float* w_output = (const float*)d_in[3];  // (2,)
    float* out = (float*)d_out;                     // (B, 2)

    int B = in_sizes[0] / NQ;

    prep_weights_kernel<<<1, 32>>>(weights);
    qsim_kernel<<<(B + 255) / 256, 256>>>(x, w_input, w_output, out, B);
}

// round 2
// speedup vs baseline: 1.0400x; 1.0400x over previous
#include <cuda_runtime.h>

// ---------------------------------------------------------------------------
// HEAQNetwork: 4-qubit, 3-layer ansatz, batch = 1M.
// TWO batch elements per thread, packed into f32x2 lanes so every gate FMA
// becomes a single FFMA2 (packed fp32 fma, 2x throughput vs scalar FFMA).
// 16 complex amplitudes (as 16+16 packed regs) live in registers.
// Qubit q maps to bit (3-q) of the amplitude index.
// ---------------------------------------------------------------------------

#define NQ 4
#define NL 3
#define QBIT(q) (1 << (3 - (q)))

typedef unsigned long long u64;

__device__ __forceinline__ u64 pk(float lo, float hi) {
    u64 r; asm("mov.b64 %0, {%1, %2};" : "=l"(r) : "f"(lo), "f"(hi)); return r;
}
__device__ __forceinline__ void upk(u64 v, float& lo, float& hi) {
    asm("mov.b64 {%0, %1}, %2;" : "=f"(lo), "=f"(hi) : "l"(v));
}
__device__ __forceinline__ u64 fma2(u64 a, u64 b, u64 c) {
    u64 r; asm("fma.rn.f32x2 %0, %1, %2, %3;" : "=l"(r) : "l"(a), "l"(b), "l"(c)); return r;
}
__device__ __forceinline__ u64 mul2(u64 a, u64 b) {
    u64 r; asm("mul.rn.f32x2 %0, %1, %2;" : "=l"(r) : "l"(a), "l"(b)); return r;
}
__device__ __forceinline__ u64 add2(u64 a, u64 b) {
    u64 r; asm("add.rn.f32x2 %0, %1, %2;" : "=l"(r) : "l"(a), "l"(b)); return r;
}
// sign-flip both lanes (LOP3 on alu pipe, stays off the fma pipe)
__device__ __forceinline__ u64 neg2(u64 a) { return a ^ 0x8000000080000000ULL; }

// RX(theta): [[c, -i s],[-i s, c]] applied to packed-batch state
template <int Q>
__device__ __forceinline__ void apply_rx(u64 sr[16], u64 si[16], u64 c2, u64 s2, u64 ns2) {
#pragma unroll
    for (int i = 0; i < 16; i++) {
        if (i & QBIT(Q)) continue;
        const int j = i | QBIT(Q);
        u64 a0r = sr[i], a0i = si[i], a1r = sr[j], a1i = si[j];
        sr[i] = fma2(s2,  a1i, mul2(c2, a0r));
        si[i] = fma2(ns2, a1r, mul2(c2, a0i));
        sr[j] = fma2(s2,  a0i, mul2(c2, a1r));
        si[j] = fma2(ns2, a0r, mul2(c2, a1i));
    }
}

// RY(theta): [[c, -s],[s, c]]
template <int Q>
__device__ __forceinline__ void apply_ry(u64 sr[16], u64 si[16], u64 c2, u64 s2, u64 ns2) {
#pragma unroll
    for (int i = 0; i < 16; i++) {
        if (i & QBIT(Q)) continue;
        const int j = i | QBIT(Q);
        u64 a0r = sr[i], a0i = si[i], a1r = sr[j], a1i = si[j];
        sr[i] = fma2(ns2, a1r, mul2(c2, a0r));
        si[i] = fma2(ns2, a1i, mul2(c2, a0i));
        sr[j] = fma2(s2,  a0r, mul2(c2, a1r));
        si[j] = fma2(s2,  a0i, mul2(c2, a1i));
    }
}

template <int C, int T>
__device__ __forceinline__ void apply_cnot(u64 sr[16], u64 si[16]) {
#pragma unroll
    for (int i = 0; i < 16; i++) {
        if (!(i & QBIT(C))) continue;
        if (i & QBIT(T)) continue;
        const int j = i | QBIT(T);
        u64 t;
        t = sr[i]; sr[i] = sr[j]; sr[j] = t;
        t = si[i]; si[i] = si[j]; si[j] = t;
    }
}

__global__ void __launch_bounds__(256)
qsim_kernel(const float4* __restrict__ x4,
            const float* __restrict__ w_input,
            const float* __restrict__ weights,
            const float* __restrict__ w_output,
            float4* __restrict__ out4,
            int B2) {
    // weight trig once per block (replaces the old prep kernel / extra graph node)
    __shared__ float s_cw[NL * NQ], s_sw[NL * NQ];
    if (threadIdx.x < NL * NQ) {
        float h = 0.5f * weights[threadIdx.x];
        s_cw[threadIdx.x] = cosf(h);
        s_sw[threadIdx.x] = sinf(h);
    }
    __syncthreads();

    int b = blockIdx.x * blockDim.x + threadIdx.x;
    if (b >= B2) return;

    // two batch elements per thread
    const float4 xa = x4[2 * b];
    const float4 xb = x4[2 * b + 1];
    const float wi0 = __ldg(&w_input[0]), wi1 = __ldg(&w_input[1]);
    const float wi2 = __ldg(&w_input[2]), wi3 = __ldg(&w_input[3]);

    // per-element RX half-angle trig: c = cos(atan(t)/2), s = sin(atan(t)/2)
    // tan-half-angle: u = t/(1+sqrt(1+t^2)); c = rsqrt(1+u^2); s = u*c
    float cae[2][4], sae[2][4];
#pragma unroll
    for (int e = 0; e < 2; e++) {
        float tq[4];
        if (e == 0) { tq[0] = xa.x * wi0; tq[1] = xa.y * wi1; tq[2] = xa.z * wi2; tq[3] = xa.w * wi3; }
        else        { tq[0] = xb.x * wi0; tq[1] = xb.y * wi1; tq[2] = xb.z * wi2; tq[3] = xb.w * wi3; }
#pragma unroll
        for (int q = 0; q < 4; q++) {
            float tt = tq[q];
            float u = tt / (1.0f + sqrtf(fmaf(tt, tt, 1.0f)));
            float r = rsqrtf(fmaf(u, u, 1.0f));
            cae[e][q] = r;
            sae[e][q] = u * r;
        }
    }
    u64 ca2[4], sa2[4], nsa2[4];
#pragma unroll
    for (int q = 0; q < 4; q++) {
        ca2[q] = pk(cae[0][q], cae[1][q]);
        sa2[q] = pk(sae[0][q], sae[1][q]);
        nsa2[q] = neg2(sa2[q]);
    }

    // ---- Layer 0 shortcut: RX+RY on |0000> is a product state.
    // v = RY(w)RX(a)|0> = (cw*ca + i*sw*sa,  sw*ca - i*cw*sa)
    u64 vr[4][2], vi[4][2];
#pragma unroll
    for (int q = 0; q < 4; q++) {
        u64 cw2 = pk(s_cw[q], s_cw[q]);
        u64 sw2 = pk(s_sw[q], s_sw[q]);
        vr[q][0] = mul2(cw2, ca2[q]);
        vi[q][0] = mul2(sw2, sa2[q]);
        vr[q][1] = mul2(sw2, ca2[q]);
        vi[q][1] = neg2(mul2(cw2, sa2[q]));
    }

    // tensor products: qubits (0,1) -> h[4]; qubits (2,3) -> l[4]
    u64 hr[4], hi[4], lr[4], li[4];
    {
        u64 nvi0[2] = { neg2(vi[0][0]), neg2(vi[0][1]) };
        u64 nvi2[2] = { neg2(vi[2][0]), neg2(vi[2][1]) };
#pragma unroll
        for (int k = 0; k < 4; k++) {
            int b0 = k >> 1, b1 = k & 1;
            hr[k] = fma2(nvi0[b0], vi[1][b1], mul2(vr[0][b0], vr[1][b1]));
            hi[k] = fma2(vi[0][b0], vr[1][b1], mul2(vr[0][b0], vi[1][b1]));
            lr[k] = fma2(nvi2[b0], vi[3][b1], mul2(vr[2][b0], vr[3][b1]));
            li[k] = fma2(vi[2][b0], vr[3][b1], mul2(vr[2][b0], vi[3][b1]));
        }
    }

    u64 sr[16], si[16];
    {
        u64 nli[4] = { neg2(li[0]), neg2(li[1]), neg2(li[2]), neg2(li[3]) };
#pragma unroll
        for (int i = 0; i < 16; i++) {
            int kh = i >> 2, kl = i & 3;
            sr[i] = fma2(hi[kh], nli[kl], mul2(hr[kh], lr[kl]));
            si[i] = fma2(hi[kh], lr[kl],  mul2(hr[kh], li[kl]));
        }
    }

    apply_cnot<0, 1>(sr, si);
    apply_cnot<1, 2>(sr, si);
    apply_cnot<2, 3>(sr, si);

    // ---- Layers 1 and 2 (RX trig reused across layers)
#pragma unroll
    for (int l = 1; l < NL; l++) {
        apply_rx<0>(sr, si, ca2[0], sa2[0], nsa2[0]);
        apply_rx<1>(sr, si, ca2[1], sa2[1], nsa2[1]);
        apply_rx<2>(sr, si, ca2[2], sa2[2], nsa2[2]);
        apply_rx<3>(sr, si, ca2[3], sa2[3], nsa2[3]);

#pragma unroll
        for (int q = 0; q < 4; q++) {
            float cw = s_cw[l * 4 + q], sw = s_sw[l * 4 + q];
            u64 cw2 = pk(cw, cw);
            u64 sw2 = pk(sw, sw);
            u64 nsw2 = neg2(sw2);
            switch (q) {
                case 0: apply_ry<0>(sr, si, cw2, sw2, nsw2); break;
                case 1: apply_ry<1>(sr, si, cw2, sw2, nsw2); break;
                case 2: apply_ry<2>(sr, si, cw2, sw2, nsw2); break;
                case 3: apply_ry<3>(sr, si, cw2, sw2, nsw2); break;
            }
        }

        apply_cnot<0, 1>(sr, si);
        apply_cnot<1, 2>(sr, si);
        apply_cnot<2, 3>(sr, si);
    }

    // ---- probabilities and <Z0>, <Z1> (packed accumulation)
    u64 ez0p = 0, ez0m = 0, ez1p = 0, ez1m = 0;  // bit pattern 0 == (0.f, 0.f)
#pragma unroll
    for (int i = 0; i < 16; i++) {
        u64 p = fma2(sr[i], sr[i], mul2(si[i], si[i]));
        if (i & 8) ez0m = add2(ez0m, p); else ez0p = add2(ez0p, p);
        if (i & 4) ez1m = add2(ez1m, p); else ez1p = add2(ez1p, p);
    }

    float e0p0, e0p1, e0m0, e0m1, e1p0, e1p1, e1m0, e1m1;
    upk(ez0p, e0p0, e0p1);
    upk(ez0m, e0m0, e0m1);
    upk(ez1p, e1p0, e1p1);
    upk(ez1m, e1m0, e1m1);

    const float wo0 = __ldg(&w_output[0]) * 0.5f;
    const float wo1 = __ldg(&w_output[1]) * 0.5f;

    float4 o;
    o.x = (1.0f + (e0p0 - e0m0)) * wo0;   // elem 2b,   out 0
    o.y = (1.0f + (e1p0 - e1m0)) * wo1;   // elem 2b,   out 1
    o.z = (1.0f + (e0p1 - e0m1)) * wo0;   // elem 2b+1, out 0
    o.w = (1.0f + (e1p1 - e1m1)) * wo1;   // elem 2b+1, out 1
    out4[b] = o;
}

extern "C" void kernel_launch(void* const* d_in, const int* in_sizes, int n_in,
                              void* d_out, int out_size) {
    const float* x        = (const float*)d_in[0];  // (B, 4)
    const float* w_input  = (const float*)d_in[1];  // (4,)
    const float* weights  = (const float*)d_in[2];  // (3, 4)
    const float* w_output = (const float*)d_in[3];  // (2,)
    float* out = (float*)d_out;                     // (B, 2)

    int B = in_sizes[0] / NQ;
    int B2 = B / 2;  // two elements per thread (B = 1,000,000 is even)

    qsim_kernel<<<(B2 + 255) / 256, 256>>>(
        (const float4*)x, w_input, weights, w_output, (float4*)out, B2);
}

// round 3
// speedup vs baseline: 1.3348x; 1.2834x over previous
#include <cuda_runtime.h>

// ---------------------------------------------------------------------------
// HEAQNetwork: 4-qubit, 3-layer ansatz, batch = 1M. One thread per element.
// Tan-form (unnormalized) gate application: every RX/RY rotation is applied as
// [[1, +-t],[+-t, 1]] (4 FMAs per amplitude pair instead of 8); the scalar
// cos factors are folded into one global normalization constant applied to the
// final probabilities. RX tan-half-angles satisfy |t|<1 (t = tan(atan(x)/2)),
// RY tan factors are shared constants precomputed per block.
// Qubit q maps to bit (3-q) of the amplitude index.
// ---------------------------------------------------------------------------

#define NQ 4
#define NL 3
#define QBIT(q) (1 << (3 - (q)))

// RX tan-form: [[1, -i t],[-i t, 1]]
template <int Q>
__device__ __forceinline__ void apply_rx_t(float sr[16], float si[16], float t, float nt) {
#pragma unroll
    for (int i = 0; i < 16; i++) {
        if (i & QBIT(Q)) continue;
        const int j = i | QBIT(Q);
        float a0r = sr[i], a0i = si[i], a1r = sr[j], a1i = si[j];
        sr[i] = fmaf(t,  a1i, a0r);
        si[i] = fmaf(nt, a1r, a0i);
        sr[j] = fmaf(t,  a0i, a1r);
        si[j] = fmaf(nt, a0r, a1i);
    }
}

// RY tan-form: [[1, -t],[t, 1]]
template <int Q>
__device__ __forceinline__ void apply_ry_t(float sr[16], float si[16], float t, float nt) {
#pragma unroll
    for (int i = 0; i < 16; i++) {
        if (i & QBIT(Q)) continue;
        const int j = i | QBIT(Q);
        float a0r = sr[i], a0i = si[i], a1r = sr[j], a1i = si[j];
        sr[i] = fmaf(nt, a1r, a0r);
        si[i] = fmaf(nt, a1i, a0i);
        sr[j] = fmaf(t,  a0r, a1r);
        si[j] = fmaf(t,  a0i, a1i);
    }
}

template <int C, int T>
__device__ __forceinline__ void apply_cnot(float sr[16], float si[16]) {
#pragma unroll
    for (int i = 0; i < 16; i++) {
        if (!(i & QBIT(C))) continue;
        if (i & QBIT(T)) continue;
        const int j = i | QBIT(T);
        float t;
        t = sr[i]; sr[i] = sr[j]; sr[j] = t;
        t = si[i]; si[i] = si[j]; si[j] = t;
    }
}

__global__ void __launch_bounds__(256)
qsim_kernel(const float4* __restrict__ x4,
            const float* __restrict__ w_input,
            const float* __restrict__ weights,
            const float* __restrict__ w_output,
            float2* __restrict__ out2,
            int B) {
    // Shared per-block constants: tan(w/2) for all 12 RY gates, and
    // K^2 = prod(cos(w/2))^2 for the global normalization.
    __shared__ float s_tw[NL * NQ];
    __shared__ float s_K2;
    if (threadIdx.x == 0) {
        float k = 1.0f;
#pragma unroll
        for (int i = 0; i < NL * NQ; i++) {
            float sc, cc;
            sincosf(0.5f * weights[i], &sc, &cc);
            s_tw[i] = sc / cc;
            k *= cc;
        }
        s_K2 = k * k;
    }
    __syncthreads();

    int b = blockIdx.x * blockDim.x + threadIdx.x;
    if (b >= B) return;

    const float4 xv = x4[b];
    const float wi0 = __ldg(&w_input[0]), wi1 = __ldg(&w_input[1]);
    const float wi2 = __ldg(&w_input[2]), wi3 = __ldg(&w_input[3]);

    // RX tan-half-angle per qubit: u = tan(atan(t)/2) = t / (1 + sqrt(1+t^2)),
    // |u| < 1 always. d = 1 + u^2 = 1/cos^2(half-angle).
    float ta[4], nta[4], d[4];
    {
        float tq[4] = { xv.x * wi0, xv.y * wi1, xv.z * wi2, xv.w * wi3 };
#pragma unroll
        for (int q = 0; q < 4; q++) {
            float t = tq[q];
            float r = sqrtf(fmaf(t, t, 1.0f));
            float u = __fdividef(t, 1.0f + r);
            ta[q] = u;
            nta[q] = -u;
            d[q] = fmaf(u, u, 1.0f);
        }
    }

    // ---- Layer 0 on |0000>: product state in tan-form.
    // RX then RY on |0>: v = (1 + i*tw*ua,  tw - i*ua)   [factor c_w*c_a dropped]
    float v0r[4], v0i[4], v1r[4], v1i[4];
#pragma unroll
    for (int q = 0; q < 4; q++) {
        float tw = s_tw[q];
        v0r[q] = 1.0f;
        v0i[q] = tw * ta[q];
        v1r[q] = tw;
        v1i[q] = nta[q];
    }

    // tensor products: qubits (0,1) -> h[4]; qubits (2,3) -> l[4]; then s[16]
    float hr[4], hi[4], lr[4], li[4];
#pragma unroll
    for (int k = 0; k < 4; k++) {
        int b0 = k >> 1, b1 = k & 1;
        float ar = b0 ? v1r[0] : v0r[0], ai = b0 ? v1i[0] : v0i[0];
        float br = b1 ? v1r[1] : v0r[1], bi = b1 ? v1i[1] : v0i[1];
        hr[k] = fmaf(-ai, bi, ar * br);
        hi[k] = fmaf( ai, br, ar * bi);
        float cr = b0 ? v1r[2] : v0r[2], ci = b0 ? v1i[2] : v0i[2];
        float dr = b1 ? v1r[3] : v0r[3], di = b1 ? v1i[3] : v0i[3];
        lr[k] = fmaf(-ci, di, cr * dr);
        li[k] = fmaf( ci, dr, cr * di);
    }

    float sr[16], si[16];
#pragma unroll
    for (int i = 0; i < 16; i++) {
        int kh = i >> 2, kl = i & 3;
        sr[i] = fmaf(-hi[kh], li[kl], hr[kh] * lr[kl]);
        si[i] = fmaf( hi[kh], lr[kl], hr[kh] * li[kl]);
    }

    apply_cnot<0, 1>(sr, si);
    apply_cnot<1, 2>(sr, si);
    apply_cnot<2, 3>(sr, si);

    // ---- Layers 1 and 2 (RX tans reused across layers)
#pragma unroll
    for (int l = 1; l < NL; l++) {
        apply_rx_t<0>(sr, si, ta[0], nta[0]);
        apply_rx_t<1>(sr, si, ta[1], nta[1]);
        apply_rx_t<2>(sr, si, ta[2], nta[2]);
        apply_rx_t<3>(sr, si, ta[3], nta[3]);

        {
            float t0 = s_tw[l * 4 + 0], t1 = s_tw[l * 4 + 1];
            float t2 = s_tw[l * 4 + 2], t3 = s_tw[l * 4 + 3];
            apply_ry_t<0>(sr, si, t0, -t0);
            apply_ry_t<1>(sr, si, t1, -t1);
            apply_ry_t<2>(sr, si, t2, -t2);
            apply_ry_t<3>(sr, si, t3, -t3);
        }

        apply_cnot<0, 1>(sr, si);
        apply_cnot<1, 2>(sr, si);
        apply_cnot<2, 3>(sr, si);
    }

    // ---- outputs. Normalized probs: p_norm = p_unnorm * C^2 with
    // C^2 = K^2 * (1/(d0 d1 d2 d3))^3   (RX factors appear once per layer x3).
    // Since sum(p_norm) = 1:  out_w = wo_w * C^2 * sum_{bit_w = 0} p_i.
    float sum0 = 0.0f, sum1 = 0.0f;
#pragma unroll
    for (int i = 0; i < 16; i++) {
        float p = fmaf(sr[i], sr[i], si[i] * si[i]);
        if (!(i & 8)) sum0 += p;   // qubit 0 = bit 3
        if (!(i & 4)) sum1 += p;   // qubit 1 = bit 2
    }

    float P = (d[0] * d[1]) * (d[2] * d[3]);
    float invP = __fdividef(1.0f, P);
    float scale = s_K2 * invP * invP * invP;

    float2 o;
    o.x = __ldg(&w_output[0]) * scale * sum0;
    o.y = __ldg(&w_output[1]) * scale * sum1;
    out2[b] = o;
}

extern "C" void kernel_launch(void* const* d_in, const int* in_sizes, int n_in,
                              void* d_out, int out_size) {
    const float* x        = (const float*)d_in[0];  // (B, 4)
    const float* w_input  = (const float*)d_in[1];  // (4,)
    const float* weights  = (const float*)d_in[2];  // (3, 4)
    const float* w_output = (const float*)d_in[3];  // (2,)
    float* out = (float*)d_out;                     // (B, 2)

    int B = in_sizes[0] / NQ;

    qsim_kernel<<<(B + 255) / 256, 256>>>(
        (const float4*)x, w_input, weights, w_output, (float2*)out, B);
}

// round 4
// speedup vs baseline: 1.4109x; 1.0570x over previous
#include <cuda_runtime.h>

// ---------------------------------------------------------------------------
// HEAQNetwork: 4-qubit, 3-layer ansatz, batch = 1M. One thread per element.
//
// Optimizations (all exact):
//  * Tan-form gates: RX/RY applied as [[1,±t],[±t,1]] (4 FMA per pair, not 8);
//    global scalars cancel in the final ratio sum/S (S = total unnorm prob).
//  * Observable transformation: final CNOT chain folded into observables
//    (Z0 -> Z0, Z1 -> Z0Z1), chain dropped.
//  * Lightcone pruning: observables are identity on qubits 2,3, so all gates
//    acting only within {2,3} after the last {0,1}<->{2,3} coupling (layer-1
//    CNOT(1,2)) are partial-trace invariant and dropped:
//      layer-1: RX3, RY3, CNOT(2,3);  layer-2: RX2, RX3, RY2, RY3, CNOTs.
//  * Layer-0 (product state) built directly with its CNOT chain folded into
//    tensor-product indexing.
//
// Qubit q maps to bit (3-q) of the amplitude index.
// ---------------------------------------------------------------------------

#define NQ 4
#define QBIT(q) (1 << (3 - (q)))

// RX tan-form: [[1, -i t],[-i t, 1]]
template <int Q>
__device__ __forceinline__ void apply_rx_t(float sr[16], float si[16], float t, float nt) {
#pragma unroll
    for (int i = 0; i < 16; i++) {
        if (i & QBIT(Q)) continue;
        const int j = i | QBIT(Q);
        float a0r = sr[i], a0i = si[i], a1r = sr[j], a1i = si[j];
        sr[i] = fmaf(t,  a1i, a0r);
        si[i] = fmaf(nt, a1r, a0i);
        sr[j] = fmaf(t,  a0i, a1r);
        si[j] = fmaf(nt, a0r, a1i);
    }
}

// RY tan-form: [[1, -t],[t, 1]]
template <int Q>
__device__ __forceinline__ void apply_ry_t(float sr[16], float si[16], float t, float nt) {
#pragma unroll
    for (int i = 0; i < 16; i++) {
        if (i & QBIT(Q)) continue;
        const int j = i | QBIT(Q);
        float a0r = sr[i], a0i = si[i], a1r = sr[j], a1i = si[j];
        sr[i] = fmaf(nt, a1r, a0r);
        si[i] = fmaf(nt, a1i, a0i);
        sr[j] = fmaf(t,  a0r, a1r);
        si[j] = fmaf(t,  a0i, a1i);
    }
}

template <int C, int T>
__device__ __forceinline__ void apply_cnot(float sr[16], float si[16]) {
#pragma unroll
    for (int i = 0; i < 16; i++) {
        if (!(i & QBIT(C))) continue;
        if (i & QBIT(T)) continue;
        const int j = i | QBIT(T);
        float t;
        t = sr[i]; sr[i] = sr[j]; sr[j] = t;
        t = si[i]; si[i] = si[j]; si[j] = t;
    }
}

__device__ __forceinline__ void cmul(float& or_, float& oi_,
                                     float ar, float ai, float br, float bi) {
    or_ = fmaf(-ai, bi, ar * br);
    oi_ = fmaf( ai, br, ar * bi);
}

__global__ void __launch_bounds__(256)
qsim_kernel(const float4* __restrict__ x4,
            const float* __restrict__ w_input,
            const float* __restrict__ weights,
            const float* __restrict__ w_output,
            float2* __restrict__ out2,
            int B) {
    // tan(w/2) for the 12 RY weights (only 0-6, 8, 9 are used after pruning).
    __shared__ float s_tw[12];
    if (threadIdx.x < 12) {
        float sc, cc;
        sincosf(0.5f * weights[threadIdx.x], &sc, &cc);
        s_tw[threadIdx.x] = __fdividef(sc, cc);
    }
    __syncthreads();

    int b = blockIdx.x * blockDim.x + threadIdx.x;
    if (b >= B) return;

    const float4 xv = x4[b];

    // RX tan-half-angles: u = tan(atan(t)/2) = t / (1 + sqrt(1+t^2)), |u| < 1.
    float ta[4], nta[4];
    {
        float tq[4] = { xv.x * __ldg(&w_input[0]), xv.y * __ldg(&w_input[1]),
                        xv.z * __ldg(&w_input[2]), xv.w * __ldg(&w_input[3]) };
#pragma unroll
        for (int q = 0; q < 4; q++) {
            float t = tq[q];
            float r = sqrtf(fmaf(t, t, 1.0f));
            float u = __fdividef(t, 1.0f + r);
            ta[q]  = u;
            nta[q] = -u;
        }
    }

    // ---- Layer 0 on |0000>: per-qubit tan-form vectors
    // v_q = RY(tw)RX(ta)|0> (scalars dropped) = (1 + i*tw*ta,  tw - i*ta)
    float vr[4][2], vi[4][2];
#pragma unroll
    for (int q = 0; q < 4; q++) {
        float tw = s_tw[q];
        vr[q][0] = 1.0f;
        vi[q][0] = tw * ta[q];
        vr[q][1] = tw;
        vi[q][1] = nta[q];
    }

    // Layer-0 CNOT chain folded into indexing:
    // s[a0a1a2a3] = v0[a0] * v1[a1^a0] * v2[a2^a1] * v3[a3^a2]
    float Er[2][2], Ei[2][2];   // E[a0][a1] = v0[a0]*v1[a1^a0]
    float gr[2][2], gi[2][2];   // g[x][y]   = v2[x]*v3[y]
#pragma unroll
    for (int a0 = 0; a0 < 2; a0++)
#pragma unroll
        for (int a1 = 0; a1 < 2; a1++) {
            cmul(Er[a0][a1], Ei[a0][a1],
                 vr[0][a0], vi[0][a0], vr[1][a1 ^ a0], vi[1][a1 ^ a0]);
            cmul(gr[a0][a1], gi[a0][a1],
                 vr[2][a0], vi[2][a0], vr[3][a1], vi[3][a1]);
        }

    float sr[16], si[16];
#pragma unroll
    for (int i = 0; i < 16; i++) {
        const int a0 = (i >> 3) & 1, a1 = (i >> 2) & 1;
        const int a2 = (i >> 1) & 1, a3 = i & 1;
        const int gx = a2 ^ a1, gy = a3 ^ a2;
        cmul(sr[i], si[i], Er[a0][a1], Ei[a0][a1], gr[gx][gy], gi[gx][gy]);
    }

    // ---- Layer 1 (pruned: no RX3/RY3/CNOT23)
    apply_rx_t<0>(sr, si, ta[0], nta[0]);
    apply_rx_t<1>(sr, si, ta[1], nta[1]);
    apply_rx_t<2>(sr, si, ta[2], nta[2]);
    {
        float t0 = s_tw[4], t1 = s_tw[5], t2 = s_tw[6];
        apply_ry_t<0>(sr, si, t0, -t0);
        apply_ry_t<1>(sr, si, t1, -t1);
        apply_ry_t<2>(sr, si, t2, -t2);
    }
    apply_cnot<0, 1>(sr, si);
    apply_cnot<1, 2>(sr, si);

    // ---- Layer 2 (pruned: only qubits 0,1; CNOT chain absorbed into observables)
    apply_rx_t<0>(sr, si, ta[0], nta[0]);
    apply_rx_t<1>(sr, si, ta[1], nta[1]);
    {
        float t0 = s_tw[8], t1 = s_tw[9];
        apply_ry_t<0>(sr, si, t0, -t0);
        apply_ry_t<1>(sr, si, t1, -t1);
    }

    // ---- Measurement.
    // out0 ~ P(q0 = 0) = (g00+g01)/S    [obs Z0]
    // out1 ~ P(q0==q1) = (g00+g11)/S    [obs Z0Z1 after CNOT-chain transform]
    float g00 = 0.0f, g01 = 0.0f, g10 = 0.0f, g11 = 0.0f;
#pragma unroll
    for (int i = 0; i < 16; i++) {
        float p = fmaf(sr[i], sr[i], si[i] * si[i]);
        switch (i >> 2) {
            case 0: g00 += p; break;
            case 1: g01 += p; break;
            case 2: g10 += p; break;
            case 3: g11 += p; break;
        }
    }
    float S    = (g00 + g01) + (g10 + g11);
    float invS = __fdividef(1.0f, S);

    float2 o;
    o.x = __ldg(&w_output[0]) * (g00 + g01) * invS;
    o.y = __ldg(&w_output[1]) * (g00 + g11) * invS;
    out2[b] = o;
}

extern "C" void kernel_launch(void* const* d_in, const int* in_sizes, int n_in,
                              void* d_out, int out_size) {
    const float* x        = (const float*)d_in[0];  // (B, 4)
    const float* w_input  = (const float*)d_in[1];  // (4,)
    const float* weights  = (const float*)d_in[2];  // (3, 4)
    const float* w_output = (const float*)d_in[3];  // (2,)
    float* out = (float*)d_out;                     // (B, 2)

    int B = in_sizes[0] / NQ;

    qsim_kernel<<<(B + 255) / 256, 256>>>(
        (const float4*)x, w_input, weights, w_output, (float2*)out, B);
}

// round 5
// speedup vs baseline: 2.3479x; 1.6642x over previous
#include <cuda_runtime.h>

// ---------------------------------------------------------------------------
// HEAQNetwork: 4-qubit, 3-layer ansatz, batch = 1M. One thread per element.
//
// Exact transformations:
//  * Tan-form gates ([[1,±t],[±t,1]]); scalar factors cancel in the final
//    ratio num/S.
//  * Final CNOT chain folded into observables (Z0 -> Z0, Z1 -> Z0Z1).
//  * Lightcone pruning: gates acting only within {2,3} after layer-1
//    CNOT(1,2) dropped (partial-trace invariant).
//  * Factored-state layer 1: after layer 0, s = E[a0][a1] * g[x][y]
//    (x=a2^a1, y=a3^a2, layer-0 CNOTs folded into the indexing).
//    RX0/RY0 act on E alone (8 ops each); RX2 acts on shared g (8 ops);
//    RY2 forks g into per-a1 copies G0/G1 (16 ops). Expansion to 16 amps
//    happens only at RX1/RY1.
//
// Qubit q maps to bit (3-q) of the amplitude index.
// ---------------------------------------------------------------------------

#define NQ 4
#define QBIT(q) (1 << (3 - (q)))

// RX tan-form on the 16-amp state: [[1, -i t],[-i t, 1]]
template <int Q>
__device__ __forceinline__ void apply_rx_t(float sr[16], float si[16], float t) {
#pragma unroll
    for (int i = 0; i < 16; i++) {
        if (i & QBIT(Q)) continue;
        const int j = i | QBIT(Q);
        float a0r = sr[i], a0i = si[i], a1r = sr[j], a1i = si[j];
        sr[i] = fmaf( t, a1i, a0r);
        si[i] = fmaf(-t, a1r, a0i);
        sr[j] = fmaf( t, a0i, a1r);
        si[j] = fmaf(-t, a0r, a1i);
    }
}

// RY tan-form on the 16-amp state: [[1, -t],[t, 1]]
template <int Q>
__device__ __forceinline__ void apply_ry_t(float sr[16], float si[16], float t) {
#pragma unroll
    for (int i = 0; i < 16; i++) {
        if (i & QBIT(Q)) continue;
        const int j = i | QBIT(Q);
        float a0r = sr[i], a0i = si[i], a1r = sr[j], a1i = si[j];
        sr[i] = fmaf(-t, a1r, a0r);
        si[i] = fmaf(-t, a1i, a0i);
        sr[j] = fmaf( t, a0r, a1r);
        si[j] = fmaf( t, a0i, a1i);
    }
}

template <int C, int T>
__device__ __forceinline__ void apply_cnot(float sr[16], float si[16]) {
#pragma unroll
    for (int i = 0; i < 16; i++) {
        if (!(i & QBIT(C))) continue;
        if (i & QBIT(T)) continue;
        const int j = i | QBIT(T);
        float t;
        t = sr[i]; sr[i] = sr[j]; sr[j] = t;
        t = si[i]; si[i] = si[j]; si[j] = t;
    }
}

__device__ __forceinline__ void cmul(float& or_, float& oi_,
                                     float ar, float ai, float br, float bi) {
    or_ = fmaf(-ai, bi, ar * br);
    oi_ = fmaf( ai, br, ar * bi);
}

__global__ void __launch_bounds__(256)
qsim_kernel(const float4* __restrict__ x4,
            const float* __restrict__ w_input,
            const float* __restrict__ weights,
            const float* __restrict__ w_output,
            float2* __restrict__ out2,
            int B) {
    // tan(w/2) for the 12 RY weights (indices 0-6, 8, 9 used after pruning).
    __shared__ float s_tw[12];
    if (threadIdx.x < 12) {
        float sc, cc;
        sincosf(0.5f * weights[threadIdx.x], &sc, &cc);
        s_tw[threadIdx.x] = __fdividef(sc, cc);
    }
    __syncthreads();

    int b = blockIdx.x * blockDim.x + threadIdx.x;
    if (b >= B) return;

    const float4 xv = x4[b];

    // RX tan-half-angles: u = tan(atan(t)/2) = t / (1 + sqrt(1+t^2)), |u| < 1.
    float ta[4];
    {
        float tq[4] = { xv.x * __ldg(&w_input[0]), xv.y * __ldg(&w_input[1]),
                        xv.z * __ldg(&w_input[2]), xv.w * __ldg(&w_input[3]) };
#pragma unroll
        for (int q = 0; q < 4; q++) {
            float t = tq[q];
            float r = sqrtf(fmaf(t, t, 1.0f));
            ta[q] = __fdividef(t, 1.0f + r);
        }
    }
    const float u0 = ta[0], u1 = ta[1], u2 = ta[2], u3 = ta[3];

    // ---- Layer 0 on |0000>: per-qubit tan-form vectors
    // v_q = RY(tw)RX(u)|0> (scalars dropped) = (1 + i*tw*u,  tw - i*u)
    float vr[4][2], vi[4][2];
#pragma unroll
    for (int q = 0; q < 4; q++) {
        float tw = s_tw[q];
        vr[q][0] = 1.0f;
        vi[q][0] = tw * ta[q];
        vr[q][1] = tw;
        vi[q][1] = -ta[q];
    }

    // E[a0][a1] = v0[a0] * v1[a1 ^ a0]   (layer-0 CNOT01 folded)
    float Er[2][2], Ei[2][2];
#pragma unroll
    for (int a0 = 0; a0 < 2; a0++)
#pragma unroll
        for (int a1 = 0; a1 < 2; a1++)
            cmul(Er[a0][a1], Ei[a0][a1],
                 vr[0][a0], vi[0][a0], vr[1][a1 ^ a0], vi[1][a1 ^ a0]);

    // g[x][y] = v2[x] * v3[y]   (x=a2^a1, y=a3^a2; CNOT12/23 folded)
    float gr[2][2], gi[2][2];
#pragma unroll
    for (int x = 0; x < 2; x++)
#pragma unroll
        for (int y = 0; y < 2; y++)
            cmul(gr[x][y], gi[x][y],
                 vr[2][x], vi[2][x], vr[3][y], vi[3][y]);

    // ---- Layer-1 gates on q0: act on E only (g independent of a0).
    // RX0:
#pragma unroll
    for (int a1 = 0; a1 < 2; a1++) {
        float e0r = Er[0][a1], e0i = Ei[0][a1];
        float e1r = Er[1][a1], e1i = Ei[1][a1];
        Er[0][a1] = fmaf( u0, e1i, e0r);
        Ei[0][a1] = fmaf(-u0, e1r, e0i);
        Er[1][a1] = fmaf( u0, e0i, e1r);
        Ei[1][a1] = fmaf(-u0, e0r, e1i);
    }
    // RY0 (t = tw[4]):
    {
        float t = s_tw[4];
#pragma unroll
        for (int a1 = 0; a1 < 2; a1++) {
            float e0r = Er[0][a1], e0i = Ei[0][a1];
            float e1r = Er[1][a1], e1i = Ei[1][a1];
            Er[0][a1] = fmaf(-t, e1r, e0r);
            Ei[0][a1] = fmaf(-t, e1i, e0i);
            Er[1][a1] = fmaf( t, e0r, e1r);
            Ei[1][a1] = fmaf( t, e0i, e1i);
        }
    }

    // ---- Layer-1 RX2 on g: flipping a2 maps (x,y)->(x^1,y^1); the tan-RX
    // matrix is symmetric, so the shared update is label-orientation free.
    float hr[2][2], hi[2][2];
#pragma unroll
    for (int x = 0; x < 2; x++)
#pragma unroll
        for (int y = 0; y < 2; y++) {
            hr[x][y] = fmaf( u2, gi[x ^ 1][y ^ 1], gr[x][y]);
            hi[x][y] = fmaf(-u2, gr[x ^ 1][y ^ 1], gi[x][y]);
        }

    // ---- Layer-1 RY2: orientation depends on a1 (a2=0 corresponds to x=a1),
    // so fork into per-a1 copies. t = tw[6].
    // G0 (a1=0): x=0 entries are the a2=0 side.
    // G1 (a1=1): x=1 entries are the a2=0 side.
    float G0r[2][2], G0i[2][2], G1r[2][2], G1i[2][2];
    {
        float t = s_tw[6];
#pragma unroll
        for (int y = 0; y < 2; y++) {
            G0r[0][y] = fmaf(-t, hr[1][y ^ 1], hr[0][y]);
            G0i[0][y] = fmaf(-t, hi[1][y ^ 1], hi[0][y]);
            G0r[1][y] = fmaf( t, hr[0][y ^ 1], hr[1][y]);
            G0i[1][y] = fmaf( t, hi[0][y ^ 1], hi[1][y]);

            G1r[1][y] = fmaf(-t, hr[0][y ^ 1], hr[1][y]);
            G1i[1][y] = fmaf(-t, hi[0][y ^ 1], hi[1][y]);
            G1r[0][y] = fmaf( t, hr[1][y ^ 1], hr[0][y]);
            G1i[0][y] = fmaf( t, hi[1][y ^ 1], hi[0][y]);
        }
    }

    // ---- Expand to 16 amplitudes: s[i] = E[a0][a1] * G_{a1}[a2^a1][a3^a2]
    float sr[16], si[16];
#pragma unroll
    for (int i = 0; i < 16; i++) {
        const int a0 = (i >> 3) & 1, a1 = (i >> 2) & 1;
        const int a2 = (i >> 1) & 1, a3 = i & 1;
        const int x = a2 ^ a1, y = a3 ^ a2;
        const float Gr = a1 ? G1r[x][y] : G0r[x][y];
        const float Gi = a1 ? G1i[x][y] : G0i[x][y];
        cmul(sr[i], si[i], Er[a0][a1], Ei[a0][a1], Gr, Gi);
    }

    // ---- Layer-1 gates on q1 (need the full state), then CNOTs (free perms)
    apply_rx_t<1>(sr, si, u1);
    apply_ry_t<1>(sr, si, s_tw[5]);
    apply_cnot<0, 1>(sr, si);
    apply_cnot<1, 2>(sr, si);

    // ---- Layer 2 (pruned to qubits 0,1; CNOT chain absorbed into observables)
    apply_rx_t<0>(sr, si, u0);
    apply_rx_t<1>(sr, si, u1);
    apply_ry_t<0>(sr, si, s_tw[8]);
    apply_ry_t<1>(sr, si, s_tw[9]);

    // ---- Measurement.
    // out0 ~ P(q0 = 0) = (g00+g01)/S    [obs Z0]
    // out1 ~ P(q0==q1) = (g00+g11)/S    [obs Z0Z1 after CNOT-chain transform]
    float g00 = 0.0f, g01 = 0.0f, g10 = 0.0f, g11 = 0.0f;
#pragma unroll
    for (int i = 0; i < 16; i++) {
        float p = fmaf(sr[i], sr[i], si[i] * si[i]);
        switch (i >> 2) {
            case 0: g00 += p; break;
            case 1: g01 += p; break;
            case 2: g10 += p; break;
            case 3: g11 += p; break;
        }
    }
    float S    = (g00 + g01) + (g10 + g11);
    float invS = __fdividef(1.0f, S);

    float2 o;
    o.x = __ldg(&w_output[0]) * (g00 + g01) * invS;
    o.y = __ldg(&w_output[1]) * (g00 + g11) * invS;
    out2[b] = o;
}

extern "C" void kernel_launch(void* const* d_in, const int* in_sizes, int n_in,
                              void* d_out, int out_size) {
    const float* x        = (const float*)d_in[0];  // (B, 4)
    const float* w_input  = (const float*)d_in[1];  // (4,)
    const float* weights  = (const float*)d_in[2];  // (3, 4)
    const float* w_output = (const float*)d_in[3];  // (2,)
    float* out = (float*)d_out;                     // (B, 2)

    int B = in_sizes[0] / NQ;

    qsim_kernel<<<(B + 255) / 256, 256>>>(
        (const float4*)x, w_input, weights, w_output, (float2*)out, B);
}

// round 8
// speedup vs baseline: 2.3765x; 1.0122x over previous
#include <cuda_runtime.h>

// ---------------------------------------------------------------------------
// HEAQNetwork: 4-qubit, 3-layer ansatz, batch = 1M. One thread per element.
//
// Exact transformations:
//  * Tan-form gates ([[1,±t],[±t,1]]); dropped scalars cancel in ratios /S.
//  * Final CNOT chain folded into observables (Z0 -> Z0, Z1 -> Z0Z1).
//  * Lightcone pruning of all {2,3}-only gates after layer-1 CNOT(1,2).
//  * Factored-state layer 0/1 (E on qubits 0,1; G fork on 2,3).
//  * Layer-2 q0 gates (RX0, RY0) pulled into the observables (Heisenberg):
//      O = cB*c0*Z0 + cB*s0*Y0 - sB*X0   (B = w8 full angle, th0 = atan(t0)),
//    evaluated via probability groups + a0-cross terms. c0 = rsqrt(1+t0^2)
//    comes free from the prologue.
//
// Qubit q maps to bit (3-q) of the amplitude index.
// ---------------------------------------------------------------------------

#define NQ 4
#define QBIT(q) (1 << (3 - (q)))

// RX tan-form on the 16-amp state: [[1, -i t],[-i t, 1]]
template <int Q>
__device__ __forceinline__ void apply_rx_t(float sr[16], float si[16], float t) {
#pragma unroll
    for (int i = 0; i < 16; i++) {
        if (i & QBIT(Q)) continue;
        const int j = i | QBIT(Q);
        float a0r = sr[i], a0i = si[i], a1r = sr[j], a1i = si[j];
        sr[i] = fmaf( t, a1i, a0r);
        si[i] = fmaf(-t, a1r, a0i);
        sr[j] = fmaf( t, a0i, a1r);
        si[j] = fmaf(-t, a0r, a1i);
    }
}

// RY tan-form on the 16-amp state: [[1, -t],[t, 1]]
template <int Q>
__device__ __forceinline__ void apply_ry_t(float sr[16], float si[16], float t) {
#pragma unroll
    for (int i = 0; i < 16; i++) {
        if (i & QBIT(Q)) continue;
        const int j = i | QBIT(Q);
        float a0r = sr[i], a0i = si[i], a1r = sr[j], a1i = si[j];
        sr[i] = fmaf(-t, a1r, a0r);
        si[i] = fmaf(-t, a1i, a0i);
        sr[j] = fmaf( t, a0r, a1r);
        si[j] = fmaf( t, a0i, a1i);
    }
}

template <int C, int T>
__device__ __forceinline__ void apply_cnot(float sr[16], float si[16]) {
#pragma unroll
    for (int i = 0; i < 16; i++) {
        if (!(i & QBIT(C))) continue;
        if (i & QBIT(T)) continue;
        const int j = i | QBIT(T);
        float t;
        t = sr[i]; sr[i] = sr[j]; sr[j] = t;
        t = si[i]; si[i] = si[j]; si[j] = t;
    }
}

__device__ __forceinline__ void cmul(float& or_, float& oi_,
                                     float ar, float ai, float br, float bi) {
    or_ = fmaf(-ai, bi, ar * br);
    oi_ = fmaf( ai, br, ar * bi);
}

__global__ void __launch_bounds__(256)
qsim_kernel(const float4* __restrict__ x4,
            const float* __restrict__ w_input,
            const float* __restrict__ weights,
            const float* __restrict__ w_output,
            float2* __restrict__ out2,
            int B) {
    // tan(w/2) for RY weights; full-angle cos/sin of weights[8] (layer-2 RY0)
    // for the observable pullback. 2*cos(w8) prefolds the factor-2 of X/Y.
    __shared__ float s_tw[12];
    __shared__ float s_c8, s_2c8, s_n2s8;
    if (threadIdx.x < 12) {
        float sc, cc;
        sincosf(0.5f * weights[threadIdx.x], &sc, &cc);
        s_tw[threadIdx.x] = __fdividef(sc, cc);
        if (threadIdx.x == 8) {
            float cfull = cc * cc - sc * sc;   // cos(w8)
            float sfull = 2.0f * sc * cc;      // sin(w8)
            s_c8   = cfull;
            s_2c8  = 2.0f * cfull;
            s_n2s8 = -2.0f * sfull;
        }
    }
    __syncthreads();

    int b = blockIdx.x * blockDim.x + threadIdx.x;
    if (b >= B) return;

    const float4 xv = x4[b];

    // RX tan-half-angles via MUFU: d = 1+t^2, rsq = rsqrt(d), r = d*rsq = sqrt(d),
    // u = t/(1+r) = tan(atan(t)/2), |u| < 1. rsq0 = cos(atan(t0)) reused below.
    float ta[4], rsq0, t0sv;
    {
        float tq[4] = { xv.x * __ldg(&w_input[0]), xv.y * __ldg(&w_input[1]),
                        xv.z * __ldg(&w_input[2]), xv.w * __ldg(&w_input[3]) };
#pragma unroll
        for (int q = 0; q < 4; q++) {
            float t = tq[q];
            float d = fmaf(t, t, 1.0f);
            float rsq = rsqrtf(d);
            float r = d * rsq;                  // sqrt(1+t^2)
            ta[q] = __fdividef(t, 1.0f + r);
            if (q == 0) { rsq0 = rsq; t0sv = t; }
        }
    }
    const float u0 = ta[0], u1 = ta[1], u2 = ta[2];

    // ---- Layer 0 on |0000>: per-qubit tan-form vectors
    // v_q = RY(tw)RX(u)|0> (scalars dropped) = (1 + i*tw*u,  tw - i*u)
    float vr[4][2], vi[4][2];
#pragma unroll
    for (int q = 0; q < 4; q++) {
        float tw = s_tw[q];
        vr[q][0] = 1.0f;
        vi[q][0] = tw * ta[q];
        vr[q][1] = tw;
        vi[q][1] = -ta[q];
    }

    // E[a0][a1] = v0[a0] * v1[a1 ^ a0]   (layer-0 CNOT01 folded)
    float Er[2][2], Ei[2][2];
#pragma unroll
    for (int a0 = 0; a0 < 2; a0++)
#pragma unroll
        for (int a1 = 0; a1 < 2; a1++)
            cmul(Er[a0][a1], Ei[a0][a1],
                 vr[0][a0], vi[0][a0], vr[1][a1 ^ a0], vi[1][a1 ^ a0]);

    // g[x][y] = v2[x] * v3[y]   (x=a2^a1, y=a3^a2; CNOT12/23 folded)
    float gr[2][2], gi[2][2];
#pragma unroll
    for (int x = 0; x < 2; x++)
#pragma unroll
        for (int y = 0; y < 2; y++)
            cmul(gr[x][y], gi[x][y],
                 vr[2][x], vi[2][x], vr[3][y], vi[3][y]);

    // ---- Layer-1 RX0 on E:
#pragma unroll
    for (int a1 = 0; a1 < 2; a1++) {
        float e0r = Er[0][a1], e0i = Ei[0][a1];
        float e1r = Er[1][a1], e1i = Ei[1][a1];
        Er[0][a1] = fmaf( u0, e1i, e0r);
        Ei[0][a1] = fmaf(-u0, e1r, e0i);
        Er[1][a1] = fmaf( u0, e0i, e1r);
        Ei[1][a1] = fmaf(-u0, e0r, e1i);
    }
    // Layer-1 RY0 (t = tw[4]):
    {
        float t = s_tw[4];
#pragma unroll
        for (int a1 = 0; a1 < 2; a1++) {
            float e0r = Er[0][a1], e0i = Ei[0][a1];
            float e1r = Er[1][a1], e1i = Ei[1][a1];
            Er[0][a1] = fmaf(-t, e1r, e0r);
            Ei[0][a1] = fmaf(-t, e1i, e0i);
            Er[1][a1] = fmaf( t, e0r, e1r);
            Ei[1][a1] = fmaf( t, e0i, e1i);
        }
    }

    // ---- Layer-1 RX2 on g (flipping a2 maps (x,y)->(x^1,y^1); symmetric matrix)
    float hr[2][2], hi[2][2];
#pragma unroll
    for (int x = 0; x < 2; x++)
#pragma unroll
        for (int y = 0; y < 2; y++) {
            hr[x][y] = fmaf( u2, gi[x ^ 1][y ^ 1], gr[x][y]);
            hi[x][y] = fmaf(-u2, gr[x ^ 1][y ^ 1], gi[x][y]);
        }

    // ---- Layer-1 RY2: orientation depends on a1 -> fork. t = tw[6].
    float G0r[2][2], G0i[2][2], G1r[2][2], G1i[2][2];
    {
        float t = s_tw[6];
#pragma unroll
        for (int y = 0; y < 2; y++) {
            G0r[0][y] = fmaf(-t, hr[1][y ^ 1], hr[0][y]);
            G0i[0][y] = fmaf(-t, hi[1][y ^ 1], hi[0][y]);
            G0r[1][y] = fmaf( t, hr[0][y ^ 1], hr[1][y]);
            G0i[1][y] = fmaf( t, hi[0][y ^ 1], hi[1][y]);

            G1r[1][y] = fmaf(-t, hr[0][y ^ 1], hr[1][y]);
            G1i[1][y] = fmaf(-t, hi[0][y ^ 1], hi[1][y]);
            G1r[0][y] = fmaf( t, hr[1][y ^ 1], hr[0][y]);
            G1i[0][y] = fmaf( t, hi[1][y ^ 1], hi[0][y]);
        }
    }

    // ---- Expand: s[i] = E[a0][a1] * G_{a1}[a2^a1][a3^a2]
    float sr[16], si[16];
#pragma unroll
    for (int i = 0; i < 16; i++) {
        const int a0 = (i >> 3) & 1, a1 = (i >> 2) & 1;
        const int a2 = (i >> 1) & 1, a3 = i & 1;
        const int x = a2 ^ a1, y = a3 ^ a2;
        const float Gr = a1 ? G1r[x][y] : G0r[x][y];
        const float Gi = a1 ? G1i[x][y] : G0i[x][y];
        cmul(sr[i], si[i], Er[a0][a1], Ei[a0][a1], Gr, Gi);
    }

    // ---- Layer-1 q1 gates, layer-1 CNOTs, then layer-2 q1 gates.
    // (Layer-2 q0 gates are pulled into the observables below.)
    apply_rx_t<1>(sr, si, u1);
    apply_ry_t<1>(sr, si, s_tw[5]);
    apply_cnot<0, 1>(sr, si);
    apply_cnot<1, 2>(sr, si);
    apply_rx_t<1>(sr, si, u1);
    apply_ry_t<1>(sr, si, s_tw[9]);

    // ---- Measurement with pulled-back q0 observable:
    //   O  = cB*c0*Z0 + cB*s0*Y0 - sB*X0          (for out0)
    //   O' = O (x) Z1                              (for out1)
    // where c0 = cos(atan t0) = rsq0, s0 = t0*rsq0, B = w8 full angle.
    float zg0 = 0.0f, zg1 = 0.0f, zg2 = 0.0f, zg3 = 0.0f;  // |amp|^2 by (a0,a1)
#pragma unroll
    for (int i = 0; i < 16; i++) {
        float p = fmaf(sr[i], sr[i], si[i] * si[i]);
        switch (i >> 2) {
            case 0: zg0 += p; break;
            case 1: zg1 += p; break;
            case 2: zg2 += p; break;
            case 3: zg3 += p; break;
        }
    }
    // a0-cross terms, split by a1:  xr = Re(conj(t0)*t1), xi = Im(conj(t0)*t1)
    float xr0 = 0.0f, xr1 = 0.0f, xi0 = 0.0f, xi1 = 0.0f;
#pragma unroll
    for (int i = 0; i < 8; i++) {
        const int j = i + 8;
        float ar = sr[i], ai = si[i], br = sr[j], bi = si[j];
        if (!(i & 4)) {
            xr0 = fmaf(ar, br, xr0); xr0 = fmaf(ai, bi, xr0);
            xi0 = fmaf(ar, bi, xi0); xi0 = fmaf(-ai, br, xi0);
        } else {
            xr1 = fmaf(ar, br, xr1); xr1 = fmaf(ai, bi, xr1);
            xi1 = fmaf(ar, bi, xi1); xi1 = fmaf(-ai, br, xi1);
        }
    }

    float p01 = zg0 + zg1, p23 = zg2 + zg3;
    float S   = p01 + p23;
    float Z0u = p01 - p23;                       // <Z0> unnorm
    float ZZu = (zg0 + zg3) - (zg1 + zg2);       // <Z0 Z1> unnorm
    float Xu  = xr0 + xr1, XZ = xr0 - xr1;       // <X0>/2, <X0 Z1>/2
    float Yu  = xi0 + xi1, YZ = xi0 - xi1;       // <Y0>/2, <Y0 Z1>/2

    float s0 = t0sv * rsq0;
    float A  = s_c8 * rsq0;     // cB * c0
    float B2 = s_2c8 * s0;      // 2 * cB * s0
    float C2 = s_n2s8;          // -2 * sB

    float O1u = fmaf(A, Z0u, fmaf(B2, Yu, C2 * Xu));
    float O2u = fmaf(A, ZZu, fmaf(B2, YZ, C2 * XZ));

    float h = 0.5f * __fdividef(1.0f, S);
    float2 o;
    o.x = __ldg(&w_output[0]) * ((S + O1u) * h);
    o.y = __ldg(&w_output[1]) * ((S + O2u) * h);
    out2[b] = o;
}

extern "C" void kernel_launch(void* const* d_in, const int* in_sizes, int n_in,
                              void* d_out, int out_size) {
    const float* x        = (const float*)d_in[0];  // (B, 4)
    const float* w_input  = (const float*)d_in[1];  // (4,)
    const float* weights  = (const float*)d_in[2];  // (3, 4)
    const float* w_output = (const float*)d_in[3];  // (2,)
    float* out = (float*)d_out;                     // (B, 2)

    int B = in_sizes[0] / NQ;

    qsim_kernel<<<(B + 255) / 256, 256>>>(
        (const float4*)x, w_input, weights, w_output, (float2*)out, B);
}